// round 11
// baseline (speedup 1.0000x reference)
#include <cuda_runtime.h>
#include <cstdint>

// RoiPoolingConv: img [1,256,256,512] f32 (NHWC), rois [1,1024,4] i32 (x1,y1,x2,y2)
// out [1,1024,7,7,512] f32 — TF1-legacy bilinear crop-resize to 7x7.
//
// R10: persistent grid-stride over the 7168 (roi,py) items with exactly
// 148*12 = 1776 resident CTAs (one wave). Removes the 64-CTA orphan wave
// (7168 = 4*1776 + 64) that left the chip latency-bound for ~3us at the end,
// and amortizes CTA ramp-up across ~4 items per block.
// Body = R8/R9: zero-weight tap dedup, 7-px full unroll, __ldg + __stcs.

#define POOL 7
#define IMG_W 256
#define IMG_C 512
#define NVEC (IMG_C / 4)   // 128 float4 per pixel

#define NUM_ITEMS (1024 * POOL)   // 7168
#define GRID_CTAS (148 * 12)      // 1776 — one full wave at 12 CTAs/SM

__global__ __launch_bounds__(NVEC, 12)
void roi_pool_persist_kernel(const float* __restrict__ img,
                             const int*   __restrict__ rois,
                             float*       __restrict__ out)
{
    const float4* __restrict__ base = reinterpret_cast<const float4*>(img);
    const int c = threadIdx.x;           // 0..127 (float4 index within channels)

    for (int item = blockIdx.x; item < NUM_ITEMS; item += GRID_CTAS) {
        const int roi = item / POOL;     // py fastest: keeps one ROI's rows
        const int py  = item - roi * POOL; // temporally adjacent (L2 tap reuse)

        // ROI descriptor: 16B aligned, uniform across block
        const int4 r = __ldg(reinterpret_cast<const int4*>(rois) + roi);
        const int x1 = r.x, y1 = r.y, x2 = r.z, y2 = r.w;

        const int hi = y2 - y1;
        const int wi = x2 - x1;
        const float h = (float)hi;
        const float w = (float)wi;

        // Reference op order: (h / P) first, then scale by index.
        const float ys = (float)py * (h / 7.0f);
        const int   y0 = (int)floorf(ys);
        const int ymax = max(hi - 1, 0);
        const int xmax = max(wi - 1, 0);
        const int  y1i = min(y0 + 1, ymax);
        const float wy = ys - (float)y0;

        // wy == 0 exactly iff py==0 or h%7==0 (7 prime, exact division for
        // multiples) -> w10=w11=0: alias row1 to row0 so those loads are
        // L1 broadcasts instead of unique DRAM rows.
        const bool wy_zero = (py == 0) || (hi % 7 == 0);
        const int row0 = y1 + y0;
        const int row1 = wy_zero ? row0 : (y1 + y1i);

        // wx == 0 for ALL px>0 iff w%7==0.
        const bool wx_zero_all = (wi % 7 == 0);

        const float4* __restrict__ b0 = base + (size_t)row0 * IMG_W * NVEC + c;
        const float4* __restrict__ b1 = base + (size_t)row1 * IMG_W * NVEC + c;

        float4* __restrict__ orow = reinterpret_cast<float4*>(out)
                                  + (size_t)item * POOL * NVEC + c;

        const float w_over_7 = w / 7.0f;

#pragma unroll
        for (int px = 0; px < POOL; ++px) {
            const float xs = (float)px * w_over_7;
            const int   x0 = (int)floorf(xs);
            const int  x1i = min(x0 + 1, xmax);
            const float wx = xs - (float)x0;

            const float w00 = (1.0f - wy) * (1.0f - wx);
            const float w01 = (1.0f - wy) * wx;
            const float w10 = wy * (1.0f - wx);
            const float w11 = wy * wx;

            const int col0 = x1 + x0;
            // px==0 folds at compile time (wx always 0 there).
            const int col1 = (px == 0 || wx_zero_all) ? col0 : (x1 + x1i);

            const float4 v00 = __ldg(b0 + (size_t)col0 * NVEC);
            const float4 v01 = __ldg(b0 + (size_t)col1 * NVEC);
            const float4 v10 = __ldg(b1 + (size_t)col0 * NVEC);
            const float4 v11 = __ldg(b1 + (size_t)col1 * NVEC);

            float4 o;
            o.x = fmaf(v00.x, w00, fmaf(v01.x, w01, fmaf(v10.x, w10, v11.x * w11)));
            o.y = fmaf(v00.y, w00, fmaf(v01.y, w01, fmaf(v10.y, w10, v11.y * w11)));
            o.z = fmaf(v00.z, w00, fmaf(v01.z, w01, fmaf(v10.z, w10, v11.z * w11)));
            o.w = fmaf(v00.w, w00, fmaf(v01.w, w01, fmaf(v10.w, w10, v11.w * w11)));

            __stcs(orow + (size_t)px * NVEC, o);
        }
    }
}

extern "C" void kernel_launch(void* const* d_in, const int* in_sizes, int n_in,
                              void* d_out, int out_size)
{
    const float* img  = (const float*)d_in[0];   // [1,256,256,512] f32
    const int*   rois = (const int*)d_in[1];     // [1,1024,4] i32
    float*       out  = (float*)d_out;           // [1,1024,7,7,512] f32

    roi_pool_persist_kernel<<<GRID_CTAS, NVEC>>>(img, rois, out);
}

// round 12
// speedup vs baseline: 1.0721x; 1.0721x over previous
#include <cuda_runtime.h>
#include <cstdint>

// RoiPoolingConv: img [1,256,256,512] f32 (NHWC), rois [1,1024,4] i32 (x1,y1,x2,y2)
// out [1,1024,7,7,512] f32 — TF1-legacy bilinear crop-resize to 7x7.
//
// R11: R9 body (zero-weight tap dedup, 7-px full unroll, __ldg + __stcs,
// 40-reg budget), but grid = 7104 = 4 * (148 SM * 12 CTA) exactly — whole
// waves only. The 64 leftover items (7168 = 7104 + 64) are folded into
// blocks 0..63 as a SECOND item: those are wave-1 blocks, so the extra work
// overlaps with a saturated chip instead of running as a 64-CTA orphan wave
// on an idle one. 99.1% of blocks run the straight-line body once.

#define POOL 7
#define IMG_W 256
#define IMG_C 512
#define NVEC (IMG_C / 4)   // 128 float4 per pixel

#define NUM_ITEMS (1024 * POOL)   // 7168
#define GRID_CTAS (148 * 12 * 4)  // 7104 — four exact waves at 12 CTAs/SM

__device__ __forceinline__
void process_item(int item, const float4* __restrict__ base,
                  const int* __restrict__ rois, float* __restrict__ out, int c)
{
    const int roi = item / POOL;
    const int py  = item - roi * POOL;

    // ROI descriptor: 16B aligned, uniform across block
    const int4 r = __ldg(reinterpret_cast<const int4*>(rois) + roi);
    const int x1 = r.x, y1 = r.y, x2 = r.z, y2 = r.w;

    const int hi = y2 - y1;
    const int wi = x2 - x1;
    const float h = (float)hi;
    const float w = (float)wi;

    // Reference op order: (h / P) first, then scale by index.
    const float ys = (float)py * (h / 7.0f);
    const int   y0 = (int)floorf(ys);
    const int ymax = max(hi - 1, 0);
    const int xmax = max(wi - 1, 0);
    const int  y1i = min(y0 + 1, ymax);
    const float wy = ys - (float)y0;

    // wy == 0 exactly iff py==0 or h%7==0 (7 prime, exact fp division for
    // multiples) -> w10=w11=0: alias row1 to row0 so those loads are L1
    // broadcasts instead of unique DRAM rows.
    const bool wy_zero = (py == 0) || (hi % 7 == 0);
    const int row0 = y1 + y0;
    const int row1 = wy_zero ? row0 : (y1 + y1i);

    // wx == 0 for ALL px>0 iff w%7==0.
    const bool wx_zero_all = (wi % 7 == 0);

    const float4* __restrict__ b0 = base + (size_t)row0 * IMG_W * NVEC + c;
    const float4* __restrict__ b1 = base + (size_t)row1 * IMG_W * NVEC + c;

    float4* __restrict__ orow = reinterpret_cast<float4*>(out)
                              + (size_t)item * POOL * NVEC + c;

    const float w_over_7 = w / 7.0f;

#pragma unroll
    for (int px = 0; px < POOL; ++px) {
        const float xs = (float)px * w_over_7;
        const int   x0 = (int)floorf(xs);
        const int  x1i = min(x0 + 1, xmax);
        const float wx = xs - (float)x0;

        const float w00 = (1.0f - wy) * (1.0f - wx);
        const float w01 = (1.0f - wy) * wx;
        const float w10 = wy * (1.0f - wx);
        const float w11 = wy * wx;

        const int col0 = x1 + x0;
        // px==0 folds at compile time (wx always 0 there).
        const int col1 = (px == 0 || wx_zero_all) ? col0 : (x1 + x1i);

        const float4 v00 = __ldg(b0 + (size_t)col0 * NVEC);
        const float4 v01 = __ldg(b0 + (size_t)col1 * NVEC);
        const float4 v10 = __ldg(b1 + (size_t)col0 * NVEC);
        const float4 v11 = __ldg(b1 + (size_t)col1 * NVEC);

        float4 o;
        o.x = fmaf(v00.x, w00, fmaf(v01.x, w01, fmaf(v10.x, w10, v11.x * w11)));
        o.y = fmaf(v00.y, w00, fmaf(v01.y, w01, fmaf(v10.y, w10, v11.y * w11)));
        o.z = fmaf(v00.z, w00, fmaf(v01.z, w01, fmaf(v10.z, w10, v11.z * w11)));
        o.w = fmaf(v00.w, w00, fmaf(v01.w, w01, fmaf(v10.w, w10, v11.w * w11)));

        __stcs(orow + (size_t)px * NVEC, o);
    }
}

__global__ __launch_bounds__(NVEC, 12)
void roi_pool_fold_kernel(const float* __restrict__ img,
                          const int*   __restrict__ rois,
                          float*       __restrict__ out)
{
    const float4* __restrict__ base = reinterpret_cast<const float4*>(img);
    const int c = threadIdx.x;           // 0..127 (float4 index within channels)

    process_item(blockIdx.x, base, rois, out, c);

    // Blocks 0..63 (wave-1 residents) absorb the 64 orphan items.
    if (blockIdx.x < (NUM_ITEMS - GRID_CTAS)) {
        process_item(GRID_CTAS + blockIdx.x, base, rois, out, c);
    }
}

extern "C" void kernel_launch(void* const* d_in, const int* in_sizes, int n_in,
                              void* d_out, int out_size)
{
    const float* img  = (const float*)d_in[0];   // [1,256,256,512] f32
    const int*   rois = (const int*)d_in[1];     // [1,1024,4] i32
    float*       out  = (float*)d_out;           // [1,1024,7,7,512] f32

    roi_pool_fold_kernel<<<GRID_CTAS, NVEC>>>(img, rois, out);
}

// round 13
// speedup vs baseline: 1.0788x; 1.0062x over previous
#include <cuda_runtime.h>
#include <cstdint>

// RoiPoolingConv: img [1,256,256,512] f32 (NHWC), rois [1,1024,4] i32 (x1,y1,x2,y2)
// out [1,1024,7,7,512] f32 — TF1-legacy bilinear crop-resize to 7x7.
//
// R11: R9 body (zero-weight tap dedup, 7-px full unroll, __ldg + __stcs,
// 40-reg budget), but grid = 7104 = 4 * (148 SM * 12 CTA) exactly — whole
// waves only. The 64 leftover items (7168 = 7104 + 64) are folded into
// blocks 0..63 as a SECOND item: those are wave-1 blocks, so the extra work
// overlaps with a saturated chip instead of running as a 64-CTA orphan wave
// on an idle one. 99.1% of blocks run the straight-line body once.

#define POOL 7
#define IMG_W 256
#define IMG_C 512
#define NVEC (IMG_C / 4)   // 128 float4 per pixel

#define NUM_ITEMS (1024 * POOL)   // 7168
#define GRID_CTAS (148 * 12 * 4)  // 7104 — four exact waves at 12 CTAs/SM

__device__ __forceinline__
void process_item(int item, const float4* __restrict__ base,
                  const int* __restrict__ rois, float* __restrict__ out, int c)
{
    const int roi = item / POOL;
    const int py  = item - roi * POOL;

    // ROI descriptor: 16B aligned, uniform across block
    const int4 r = __ldg(reinterpret_cast<const int4*>(rois) + roi);
    const int x1 = r.x, y1 = r.y, x2 = r.z, y2 = r.w;

    const int hi = y2 - y1;
    const int wi = x2 - x1;
    const float h = (float)hi;
    const float w = (float)wi;

    // Reference op order: (h / P) first, then scale by index.
    const float ys = (float)py * (h / 7.0f);
    const int   y0 = (int)floorf(ys);
    const int ymax = max(hi - 1, 0);
    const int xmax = max(wi - 1, 0);
    const int  y1i = min(y0 + 1, ymax);
    const float wy = ys - (float)y0;

    // wy == 0 exactly iff py==0 or h%7==0 (7 prime, exact fp division for
    // multiples) -> w10=w11=0: alias row1 to row0 so those loads are L1
    // broadcasts instead of unique DRAM rows.
    const bool wy_zero = (py == 0) || (hi % 7 == 0);
    const int row0 = y1 + y0;
    const int row1 = wy_zero ? row0 : (y1 + y1i);

    // wx == 0 for ALL px>0 iff w%7==0.
    const bool wx_zero_all = (wi % 7 == 0);

    const float4* __restrict__ b0 = base + (size_t)row0 * IMG_W * NVEC + c;
    const float4* __restrict__ b1 = base + (size_t)row1 * IMG_W * NVEC + c;

    float4* __restrict__ orow = reinterpret_cast<float4*>(out)
                              + (size_t)item * POOL * NVEC + c;

    const float w_over_7 = w / 7.0f;

#pragma unroll
    for (int px = 0; px < POOL; ++px) {
        const float xs = (float)px * w_over_7;
        const int   x0 = (int)floorf(xs);
        const int  x1i = min(x0 + 1, xmax);
        const float wx = xs - (float)x0;

        const float w00 = (1.0f - wy) * (1.0f - wx);
        const float w01 = (1.0f - wy) * wx;
        const float w10 = wy * (1.0f - wx);
        const float w11 = wy * wx;

        const int col0 = x1 + x0;
        // px==0 folds at compile time (wx always 0 there).
        const int col1 = (px == 0 || wx_zero_all) ? col0 : (x1 + x1i);

        const float4 v00 = __ldg(b0 + (size_t)col0 * NVEC);
        const float4 v01 = __ldg(b0 + (size_t)col1 * NVEC);
        const float4 v10 = __ldg(b1 + (size_t)col0 * NVEC);
        const float4 v11 = __ldg(b1 + (size_t)col1 * NVEC);

        float4 o;
        o.x = fmaf(v00.x, w00, fmaf(v01.x, w01, fmaf(v10.x, w10, v11.x * w11)));
        o.y = fmaf(v00.y, w00, fmaf(v01.y, w01, fmaf(v10.y, w10, v11.y * w11)));
        o.z = fmaf(v00.z, w00, fmaf(v01.z, w01, fmaf(v10.z, w10, v11.z * w11)));
        o.w = fmaf(v00.w, w00, fmaf(v01.w, w01, fmaf(v10.w, w10, v11.w * w11)));

        __stcs(orow + (size_t)px * NVEC, o);
    }
}

__global__ __launch_bounds__(NVEC, 12)
void roi_pool_fold_kernel(const float* __restrict__ img,
                          const int*   __restrict__ rois,
                          float*       __restrict__ out)
{
    const float4* __restrict__ base = reinterpret_cast<const float4*>(img);
    const int c = threadIdx.x;           // 0..127 (float4 index within channels)

    process_item(blockIdx.x, base, rois, out, c);

    // Blocks 0..63 (wave-1 residents) absorb the 64 orphan items.
    if (blockIdx.x < (NUM_ITEMS - GRID_CTAS)) {
        process_item(GRID_CTAS + blockIdx.x, base, rois, out, c);
    }
}

extern "C" void kernel_launch(void* const* d_in, const int* in_sizes, int n_in,
                              void* d_out, int out_size)
{
    const float* img  = (const float*)d_in[0];   // [1,256,256,512] f32
    const int*   rois = (const int*)d_in[1];     // [1,1024,4] i32
    float*       out  = (float*)d_out;           // [1,1024,7,7,512] f32

    roi_pool_fold_kernel<<<GRID_CTAS, NVEC>>>(img, rois, out);
}